// round 13
// baseline (speedup 1.0000x reference)
#include <cuda_runtime.h>
#include <cuda_bf16.h>
#include <cstdint>

// ============================================================================
// SelfAttention R13:
//   - QKV-projection + score GEMMs: int8 two-term fixed-point split
//     (a = s_row*(128*A1 + A0)), mma.m16n8k32.s8, exact int32 accumulation,
//     3 MMA passes (A1B1 -> acc11, A1B0+A0B1 -> accX), epilogue combines
//     16384*acc11 + 128*accX with per-row scales.
//   - O GEMM stays bf16x3 (peaked softmax rows amplify int8 quant error).
//   - quant kernels: per-row absmax (warp/row), scales stored per row.
// ============================================================================

constexpr int S = 2048, D = 1024, NB = 4;
constexpr long SD  = (long)S * D;
constexpr long SSZ = (long)S * S;
constexpr long NX = (long)NB * S * D;      // 8,388,608
constexpr long NW = (long)D * D;
constexpr long NP = (long)NB * S * S;

// int8 plane offsets
constexpr long I_X1 = 0, I_X0 = NX;
constexpr long I_WQ1 = 2*NX,        I_WQ0 = I_WQ1+NW,
               I_WK1 = I_WQ1+2*NW,  I_WK0 = I_WQ1+3*NW,
               I_WV1 = I_WQ1+4*NW,  I_WV0 = I_WQ1+5*NW;
constexpr long I_Q1 = 2*NX+6*NW, I_Q0 = I_Q1+NX, I_K1 = I_Q1+2*NX, I_K0 = I_Q1+3*NX;
constexpr long NI8 = 6*NX + 6*NW;
__device__ __align__(128) int8_t g_i8[NI8];

// bf16 planes: VT hi/lo, P hi/lo
constexpr long OVTH = 0, OVTL = NX, OPH = 2*NX, OPL = 2*NX + NP;
__device__ __align__(128) __nv_bfloat16 g_bf[2*NX + 2*NP];

__device__ float g_sc[NP];     // Q fp32 [0:NX), K fp32 [NX:2NX) then scores

// per-row scales
constexpr long SX = 0, SWQ = 8192, SWK = 9216, SWV = 10240,
               SQ = 11264, SK = 19456, NSCALE = 27648;
__device__ float g_scale[NSCALE];

#define SWZ(o) ((o) ^ (((o) >> 3) & 0x70))

// ---------------------------------------------------------------- helpers
__device__ __forceinline__ uint32_t smem_u32(const void* p) {
    uint32_t a;
    asm("{ .reg .u64 t; cvta.to.shared.u64 t, %1; cvt.u32.u64 %0, t; }"
        : "=r"(a) : "l"(p));
    return a;
}
__device__ __forceinline__ void ldsm4(uint32_t* r, uint32_t addr) {
    asm volatile("ldmatrix.sync.aligned.m8n8.x4.shared.b16 {%0,%1,%2,%3}, [%4];"
                 : "=r"(r[0]), "=r"(r[1]), "=r"(r[2]), "=r"(r[3]) : "r"(addr));
}
__device__ __forceinline__ void mma16816(float* d, const uint32_t* a,
                                         const uint32_t* b) {
    asm volatile(
        "mma.sync.aligned.m16n8k16.row.col.f32.bf16.bf16.f32 "
        "{%0,%1,%2,%3}, {%4,%5,%6,%7}, {%8,%9}, {%0,%1,%2,%3};"
        : "+f"(d[0]), "+f"(d[1]), "+f"(d[2]), "+f"(d[3])
        : "r"(a[0]), "r"(a[1]), "r"(a[2]), "r"(a[3]), "r"(b[0]), "r"(b[1]));
}
__device__ __forceinline__ void mma_s8(int* d, const uint32_t* a,
                                       const uint32_t* b) {
    asm volatile(
        "mma.sync.aligned.m16n8k32.row.col.s32.s8.s8.s32 "
        "{%0,%1,%2,%3}, {%4,%5,%6,%7}, {%8,%9}, {%0,%1,%2,%3};"
        : "+r"(d[0]), "+r"(d[1]), "+r"(d[2]), "+r"(d[3])
        : "r"(a[0]), "r"(a[1]), "r"(a[2]), "r"(a[3]), "r"(b[0]), "r"(b[1]));
}
#define CPA16(dst, src) \
    asm volatile("cp.async.cg.shared.global [%0], [%1], 16;" \
                 :: "r"(dst), "l"(src) : "memory")
#define CP_COMMIT() asm volatile("cp.async.commit_group;" ::: "memory")

__device__ __forceinline__ void split2(float v0, float v1,
                                       uint32_t& h, uint32_t& l) {
    __nv_bfloat16 h0 = __float2bfloat16_rn(v0), h1 = __float2bfloat16_rn(v1);
    __nv_bfloat162 hh(h0, h1);
    __nv_bfloat162 ll(__float2bfloat16_rn(v0 - __bfloat162float(h0)),
                      __float2bfloat16_rn(v1 - __bfloat162float(h1)));
    h = *reinterpret_cast<uint32_t*>(&hh);
    l = *reinterpret_cast<uint32_t*>(&ll);
}

// ---------------------------------------------------------------- quant
// Per-row (length 1024) absmax quantization to two int8 planes + scale.
// 1 warp per row, 8 rows per CTA.
__global__ void __launch_bounds__(256)
quant_rows(const float* __restrict__ src, int8_t* __restrict__ hi,
           int8_t* __restrict__ lo, float* __restrict__ scale, int nrows)
{
    const int lane = threadIdx.x & 31;
    const int row = blockIdx.x * 8 + (threadIdx.x >> 5);
    if (row >= nrows) return;
    const float* p = src + (long)row * 1024;

    float4 v[8];
    float m = 0.f;
#pragma unroll
    for (int j = 0; j < 8; j++) {
        v[j] = *reinterpret_cast<const float4*>(p + lane * 4 + 128 * j);
        m = fmaxf(m, fmaxf(fmaxf(fabsf(v[j].x), fabsf(v[j].y)),
                           fmaxf(fabsf(v[j].z), fabsf(v[j].w))));
    }
#pragma unroll
    for (int o = 16; o > 0; o >>= 1)
        m = fmaxf(m, __shfl_xor_sync(0xffffffffu, m, o));
    const float inv = m > 0.f ? 16256.f / m : 0.f;
    if (lane == 0) scale[row] = m * (1.f / 16256.f);

    uint32_t* h32 = reinterpret_cast<uint32_t*>(hi + (long)row * 1024);
    uint32_t* l32 = reinterpret_cast<uint32_t*>(lo + (long)row * 1024);
#pragma unroll
    for (int j = 0; j < 8; j++) {
        const float e[4] = { v[j].x, v[j].y, v[j].z, v[j].w };
        uint32_t hw = 0, lw = 0;
#pragma unroll
        for (int k = 0; k < 4; k++) {
            float t = e[k] * inv;
            float a1 = rintf(t * 0.0078125f);        // /128
            float a0 = rintf(t - 128.f * a1);
            hw |= ((uint32_t)((int)a1) & 0xFFu) << (8 * k);
            lw |= ((uint32_t)((int)a0) & 0xFFu) << (8 * k);
        }
        h32[lane + 32 * j] = hw;
        l32[lane + 32 * j] = lw;
    }
}

// ---------------------------------------------------------------- i8 mainloop
// 512 thr, 16 warps (4m x 4n), warp 32x32, CTA 128x128, K-chunk 64 int8.
// Stage 32KB: A rows 128 x [A1 64B | A0 64B] swizzled; B at +16384.
constexpr int STG8 = 32 * 1024;
constexpr int OFB8 = 16384;
constexpr int SMEM_I8 = 3 * STG8 + 1024;

__device__ __forceinline__ void gemm_mainloop_i8(
    const int8_t* __restrict__ gA1, const int8_t* __restrict__ gA0,
    const int8_t* __restrict__ gB1, const int8_t* __restrict__ gB0,
    int lda, int ldb, int K, uint32_t abase, int* acc11, int* accX)
{
    const int tid = threadIdx.x, lane = tid & 31, wid = tid >> 5;

    // loader: thread -> (arr, row, plane); 4 x 16B per thread per chunk
    const int p = tid & 1, r = (tid >> 1) & 127, arr = tid >> 8;
    const int8_t* src = arr ? ((p ? gB0 : gB1) + (long)r * ldb)
                            : ((p ? gA0 : gA1) + (long)r * lda);
    uint32_t dst[4];
#pragma unroll
    for (int q = 0; q < 4; q++)
        dst[q] = (uint32_t)(arr * OFB8) + SWZ((uint32_t)r * 128 + p * 64 + q * 16);

    // fragment constants
    const int mw = (wid >> 2) * 32, nw = (wid & 3) * 32;
    uint32_t arow[2], aswz[2], brow[2], bswz[2];
#pragma unroll
    for (int i = 0; i < 2; i++) {
        const uint32_t ra =
            (uint32_t)(mw + 16 * i + (lane & 7) + 8 * ((lane >> 3) & 1)) * 128;
        arow[i] = ra; aswz[i] = (ra >> 3) & 0x70;
        const uint32_t rb =
            (uint32_t)(nw + 16 * i + (lane & 7) + 8 * ((lane >> 4) & 1)) * 128;
        brow[i] = rb; bswz[i] = (rb >> 3) & 0x70;
    }
    const uint32_t ac16 = (uint32_t)(16 * ((lane >> 4) & 1));
    const uint32_t bc16 = (uint32_t)(16 * ((lane >> 3) & 1));

    const int nch = K >> 6;

#define ISSUE8(ch) do {                                                       \
        const uint32_t _sb = abase + (uint32_t)((ch) % 3) * STG8;             \
        const long _k = (long)(ch) * 64;                                      \
        _Pragma("unroll")                                                     \
        for (int q = 0; q < 4; q++) CPA16(_sb + dst[q], src + _k + q * 16);   \
        CP_COMMIT();                                                          \
    } while (0)

    ISSUE8(0);
    ISSUE8(1);

    for (int ch = 0; ch < nch; ch++) {
        if (ch + 1 < nch)
            asm volatile("cp.async.wait_group 1;" ::: "memory");
        else
            asm volatile("cp.async.wait_group 0;" ::: "memory");
        __syncthreads();
        if (ch + 2 < nch) ISSUE8(ch + 2);

        const uint32_t sb = abase + (uint32_t)(ch % 3) * STG8;
#pragma unroll
        for (int ks = 0; ks < 2; ks++) {
            const uint32_t cb = (uint32_t)ks * 32;
            uint32_t af[2][4], bh[8], bl[8];
            // B1 (plane offset 0), B0 (plane offset 64)
#pragma unroll
            for (int j = 0; j < 2; j++) {
                ldsm4(&bh[4 * j], sb + OFB8 + brow[j] + ((cb + bc16) ^ bswz[j]));
                ldsm4(&bl[4 * j], sb + OFB8 + brow[j] + ((cb + 64 + bc16) ^ bswz[j]));
            }
#pragma unroll
            for (int i = 0; i < 2; i++)   // A1
                ldsm4(af[i], sb + arow[i] + ((cb + ac16) ^ aswz[i]));
#pragma unroll
            for (int i = 0; i < 2; i++)
#pragma unroll
                for (int j = 0; j < 4; j++)
                    mma_s8(acc11 + (i * 4 + j) * 4, af[i], &bh[j * 2]); // A1B1
#pragma unroll
            for (int i = 0; i < 2; i++)
#pragma unroll
                for (int j = 0; j < 4; j++)
                    mma_s8(accX + (i * 4 + j) * 4, af[i], &bl[j * 2]);  // A1B0
#pragma unroll
            for (int i = 0; i < 2; i++)   // A0 (reuse regs)
                ldsm4(af[i], sb + arow[i] + ((cb + 64 + ac16) ^ aswz[i]));
#pragma unroll
            for (int i = 0; i < 2; i++)
#pragma unroll
                for (int j = 0; j < 4; j++)
                    mma_s8(accX + (i * 4 + j) * 4, af[i], &bh[j * 2]);  // A0B1
        }
    }
#undef ISSUE8
}

// ---------------------------------------------------------------- i8 QKV
// grid (8, 64, 3): z=0 -> Q fp32 (g_sc), z=1 -> K fp32 (g_sc+NX),
// z=2 -> VT bf16 pairs (transposed, smem-staged).
__global__ void __launch_bounds__(512, 1)
qkv_i8(const float* __restrict__ bq, const float* __restrict__ bk,
       const float* __restrict__ bv)
{
    const int z = blockIdx.z;
    const long row0 = (long)blockIdx.y * 128, col0 = (long)blockIdx.x * 128;

    extern __shared__ char smem_raw[];
    const uint32_t rawb  = smem_u32(smem_raw);
    const uint32_t abase = (rawb + 1023) & ~1023u;
    char* smem = smem_raw + (abase - rawb);

    const long w1 = z == 0 ? I_WQ1 : z == 1 ? I_WK1 : I_WV1;
    const long w0 = z == 0 ? I_WQ0 : z == 1 ? I_WK0 : I_WV0;
    const long sw = z == 0 ? SWQ : z == 1 ? SWK : SWV;
    const float* bias = z == 0 ? bq : z == 1 ? bk : bv;

    int acc11[32], accX[32];
#pragma unroll
    for (int i = 0; i < 32; i++) { acc11[i] = 0; accX[i] = 0; }

    gemm_mainloop_i8(&g_i8[I_X1] + row0 * D, &g_i8[I_X0] + row0 * D,
                     &g_i8[w1] + col0 * D, &g_i8[w0] + col0 * D,
                     D, D, D, abase, acc11, accX);

    const int tid = threadIdx.x, lane = tid & 31, wid = tid >> 5;
    const int mw = (wid >> 2) * 32, nw = (wid & 3) * 32;
    const int qr = lane >> 2, qc = lane & 3;

    if (z < 2) {
        float* dstf = g_sc + (z == 0 ? 0 : NX);
#pragma unroll
        for (int i = 0; i < 2; i++)
#pragma unroll
            for (int h = 0; h < 2; h++) {
                const int rl = mw + 16 * i + qr + 8 * h;
                const float sa = g_scale[SX + row0 + rl];
#pragma unroll
                for (int j = 0; j < 4; j++) {
                    const int idx = (i * 4 + j) * 4 + 2 * h;
                    const long c = col0 + nw + 8 * j + 2 * qc;
                    const float sb0 = g_scale[sw + c], sb1 = g_scale[sw + c + 1];
                    float c0 = fmaf(16384.f, (float)acc11[idx],
                                    128.f * (float)accX[idx]);
                    float c1 = fmaf(16384.f, (float)acc11[idx + 1],
                                    128.f * (float)accX[idx + 1]);
                    float v0 = c0 * sa * sb0 + bias[c];
                    float v1 = c1 * sa * sb1 + bias[c + 1];
                    *reinterpret_cast<float2*>(&dstf[(row0 + rl) * D + c]) =
                        make_float2(v0, v1);
                }
            }
    } else {
        const long b = row0 >> 11, rloc = row0 & (S - 1);
        __nv_bfloat16* Ch = &g_bf[OVTH] + b * SD;
        __nv_bfloat16* Cl = &g_bf[OVTL] + b * SD;
        __syncthreads();
        __nv_bfloat16* sh = reinterpret_cast<__nv_bfloat16*>(smem);
        __nv_bfloat16* sl = sh + 128 * 136;
#pragma unroll
        for (int i = 0; i < 2; i++)
#pragma unroll
            for (int h = 0; h < 2; h++) {
                const int rl = mw + 16 * i + qr + 8 * h;
                const float sa = g_scale[SX + row0 + rl];
#pragma unroll
                for (int j = 0; j < 4; j++) {
                    const int idx = (i * 4 + j) * 4 + 2 * h;
                    const int cl = nw + 8 * j + 2 * qc;
                    const float sb0 = g_scale[sw + col0 + cl];
                    const float sb1 = g_scale[sw + col0 + cl + 1];
                    float v0 = fmaf(16384.f, (float)acc11[idx],
                                    128.f * (float)accX[idx]) * sa * sb0
                               + bias[col0 + cl];
                    float v1 = fmaf(16384.f, (float)acc11[idx + 1],
                                    128.f * (float)accX[idx + 1]) * sa * sb1
                               + bias[col0 + cl + 1];
                    __nv_bfloat16 h0 = __float2bfloat16_rn(v0);
                    __nv_bfloat16 h1 = __float2bfloat16_rn(v1);
                    sh[cl * 136 + rl]       = h0;
                    sh[(cl + 1) * 136 + rl] = h1;
                    sl[cl * 136 + rl] =
                        __float2bfloat16_rn(v0 - __bfloat162float(h0));
                    sl[(cl + 1) * 136 + rl] =
                        __float2bfloat16_rn(v1 - __bfloat162float(h1));
                }
            }
        __syncthreads();
        const int c = tid >> 2, seg = tid & 3;
        const __nv_bfloat16* srh = sh + c * 136 + seg * 32;
        const __nv_bfloat16* srl = sl + c * 136 + seg * 32;
        __nv_bfloat16* dsh = Ch + (col0 + c) * (long)S + rloc + seg * 32;
        __nv_bfloat16* dsl = Cl + (col0 + c) * (long)S + rloc + seg * 32;
#pragma unroll
        for (int q = 0; q < 4; q++) {
            *reinterpret_cast<uint4*>(dsh + q * 8) =
                *reinterpret_cast<const uint4*>(srh + q * 8);
            *reinterpret_cast<uint4*>(dsl + q * 8) =
                *reinterpret_cast<const uint4*>(srl + q * 8);
        }
    }
}

// ---------------------------------------------------------------- i8 scores
// grid (16, 16, NB): Sc = Q@K^T / 32, fp32 -> g_sc (scores overwrite Q/K fp32)
__global__ void __launch_bounds__(512, 1)
score_i8()
{
    const long zb = blockIdx.z;
    const long row0 = (long)blockIdx.y * 128, col0 = (long)blockIdx.x * 128;

    extern __shared__ char smem_raw[];
    const uint32_t rawb  = smem_u32(smem_raw);
    const uint32_t abase = (rawb + 1023) & ~1023u;

    int acc11[32], accX[32];
#pragma unroll
    for (int i = 0; i < 32; i++) { acc11[i] = 0; accX[i] = 0; }

    const long aoff = (zb * S + row0) * D, boff = (zb * S + col0) * D;
    gemm_mainloop_i8(&g_i8[I_Q1] + aoff, &g_i8[I_Q0] + aoff,
                     &g_i8[I_K1] + boff, &g_i8[I_K0] + boff,
                     D, D, D, abase, acc11, accX);

    float* Cp = g_sc + zb * SSZ;
    const int tid = threadIdx.x, lane = tid & 31, wid = tid >> 5;
    const int mw = (wid >> 2) * 32, nw = (wid & 3) * 32;
    const int qr = lane >> 2, qc = lane & 3;
#pragma unroll
    for (int i = 0; i < 2; i++)
#pragma unroll
        for (int h = 0; h < 2; h++) {
            const int rl = mw + 16 * i + qr + 8 * h;
            const float sa = g_scale[SQ + zb * S + row0 + rl] * 0.03125f;
#pragma unroll
            for (int j = 0; j < 4; j++) {
                const int idx = (i * 4 + j) * 4 + 2 * h;
                const long c = col0 + nw + 8 * j + 2 * qc;
                const float sb0 = g_scale[SK + zb * S + c];
                const float sb1 = g_scale[SK + zb * S + c + 1];
                float v0 = fmaf(16384.f, (float)acc11[idx],
                                128.f * (float)accX[idx]) * sa * sb0;
                float v1 = fmaf(16384.f, (float)acc11[idx + 1],
                                128.f * (float)accX[idx + 1]) * sa * sb1;
                *reinterpret_cast<float2*>(&Cp[(row0 + rl) * (long)S + c]) =
                    make_float2(v0, v1);
            }
        }
}

// ---------------------------------------------------------------- bf16 O GEMM
constexpr int STAGE  = 64 * 1024;
constexpr int OFF_AH = 0, OFF_AL = 16384, OFF_BH = 32768, OFF_BL = 49152;
constexpr int SMEM_BF = 3 * STAGE + 1024;

__device__ __forceinline__ void gemm_mainloop_bf(
    const __nv_bfloat16* __restrict__ gAh, const __nv_bfloat16* __restrict__ gAl,
    const __nv_bfloat16* __restrict__ gBh, const __nv_bfloat16* __restrict__ gBl,
    int lda, int ldb, int K, uint32_t abase, float* acc)
{
    const int tid = threadIdx.x, lane = tid & 31, wid = tid >> 5;

    const int r0 = tid >> 3, s0 = tid & 7;
    const uint32_t w0 = SWZ((uint32_t)r0 * 128 + s0 * 16);
    const uint32_t w1 = SWZ((uint32_t)(r0 + 64) * 128 + s0 * 16);
    const __nv_bfloat16* ga[8] = {
        gAh + (long)r0 * lda + s0 * 8,
        gAh + (long)(r0 + 64) * lda + s0 * 8,
        gAl + (long)r0 * lda + s0 * 8,
        gAl + (long)(r0 + 64) * lda + s0 * 8,
        gBh + (long)r0 * ldb + s0 * 8,
        gBh + (long)(r0 + 64) * ldb + s0 * 8,
        gBl + (long)r0 * ldb + s0 * 8,
        gBl + (long)(r0 + 64) * ldb + s0 * 8 };
    const uint32_t soff[8] = { OFF_AH + w0, OFF_AH + w1, OFF_AL + w0, OFF_AL + w1,
                               OFF_BH + w0, OFF_BH + w1, OFF_BL + w0, OFF_BL + w1 };

    const int mw = (wid >> 2) * 32, nw = (wid & 3) * 32;
    uint32_t a_row[2], a_swz[2];
#pragma unroll
    for (int i = 0; i < 2; i++) {
        uint32_t rb = (uint32_t)(mw + 16 * i + (lane & 15)) * 128;
        a_row[i] = rb; a_swz[i] = (rb >> 3) & 0x70;
    }
    const uint32_t a_kl = (uint32_t)((lane >> 4) << 4);
    uint32_t b_row[2], b_swz[2];
#pragma unroll
    for (int p = 0; p < 2; p++) {
        uint32_t rb = (uint32_t)(nw + 16 * p + (lane & 7) + ((lane & 16) >> 1)) * 128;
        b_row[p] = rb; b_swz[p] = (rb >> 3) & 0x70;
    }
    const uint32_t b_kl = (uint32_t)((lane & 8) << 1);

    const int nch = K >> 6;

#define ISSUEB(ch) do {                                                       \
        const uint32_t _sb = abase + (uint32_t)((ch) % 3) * STAGE;            \
        const long _k = (long)(ch) * 64;                                      \
        _Pragma("unroll")                                                     \
        for (int q = 0; q < 8; q++) CPA16(_sb + soff[q], ga[q] + _k);         \
        CP_COMMIT();                                                          \
    } while (0)

    ISSUEB(0);
    ISSUEB(1);

    for (int ch = 0; ch < nch; ch++) {
        if (ch + 1 < nch)
            asm volatile("cp.async.wait_group 1;" ::: "memory");
        else
            asm volatile("cp.async.wait_group 0;" ::: "memory");
        __syncthreads();
        if (ch + 2 < nch) ISSUEB(ch + 2);

        const uint32_t sb = abase + (uint32_t)(ch % 3) * STAGE;
#pragma unroll
        for (int ks = 0; ks < 4; ks++) {
            const uint32_t KB = ks * 32;
            uint32_t af[2][4], bh[8], bl[8];
#pragma unroll
            for (int i = 0; i < 2; i++)
                ldsm4(af[i], sb + OFF_AH + a_row[i] + ((KB + a_kl) ^ a_swz[i]));
#pragma unroll
            for (int p = 0; p < 2; p++) {
                const uint32_t ko = KB + b_kl;
                ldsm4(&bh[4 * p], sb + OFF_BH + b_row[p] + (ko ^ b_swz[p]));
                ldsm4(&bl[4 * p], sb + OFF_BL + b_row[p] + (ko ^ b_swz[p]));
            }
#pragma unroll
            for (int i = 0; i < 2; i++)
#pragma unroll
                for (int j = 0; j < 4; j++)
                    mma16816(acc + (i * 4 + j) * 4, af[i], &bh[j * 2]);
#pragma unroll
            for (int i = 0; i < 2; i++)
#pragma unroll
                for (int j = 0; j < 4; j++)
                    mma16816(acc + (i * 4 + j) * 4, af[i], &bl[j * 2]);
#pragma unroll
            for (int i = 0; i < 2; i++)
                ldsm4(af[i], sb + OFF_AL + a_row[i] + ((KB + a_kl) ^ a_swz[i]));
#pragma unroll
            for (int i = 0; i < 2; i++)
#pragma unroll
                for (int j = 0; j < 4; j++)
                    mma16816(acc + (i * 4 + j) * 4, af[i], &bh[j * 2]);
        }
    }
#undef ISSUEB
}

__global__ void __launch_bounds__(512, 1)
mma_o(float* __restrict__ out)
{
    const long zb = blockIdx.z;
    const long row0 = (long)blockIdx.y * 128, col0 = (long)blockIdx.x * 128;

    extern __shared__ char smem_raw[];
    const uint32_t rawb  = smem_u32(smem_raw);
    const uint32_t abase = (rawb + 1023) & ~1023u;

    float acc[32];
#pragma unroll
    for (int i = 0; i < 32; i++) acc[i] = 0.f;

    gemm_mainloop_bf(&g_bf[OPH] + zb * SSZ + row0 * S,
                     &g_bf[OPL] + zb * SSZ + row0 * S,
                     &g_bf[OVTH] + zb * SD + col0 * S,
                     &g_bf[OVTL] + zb * SD + col0 * S,
                     S, S, S, abase, acc);

    float* Cp = out + zb * SD;
    const int tid = threadIdx.x, lane = tid & 31, wid = tid >> 5;
    const int mw = (wid >> 2) * 32, nw = (wid & 3) * 32;
    const int qr = lane >> 2, qc = lane & 3;
#pragma unroll
    for (int i = 0; i < 2; i++)
#pragma unroll
        for (int j = 0; j < 4; j++) {
            const float* d = acc + (i * 4 + j) * 4;
#pragma unroll
            for (int h = 0; h < 2; h++) {
                const long r = row0 + mw + 16 * i + qr + 8 * h;
                const long c = col0 + nw + 8 * j + 2 * qc;
                *reinterpret_cast<float2*>(&Cp[r * (long)D + c]) =
                    make_float2(d[2 * h], d[2 * h + 1]);
            }
        }
}

// ---------------------------------------------------------------- softmax
__global__ void __launch_bounds__(256)
softmax_rows(const float* __restrict__ sc, __nv_bfloat16* __restrict__ ph,
             __nv_bfloat16* __restrict__ pl)
{
    const long ro = (long)blockIdx.x * 2048;
    const float* p = sc + ro;
    __shared__ float red[8];
    const int t = threadIdx.x, lane = t & 31, w = t >> 5;

    float v[8];
    *reinterpret_cast<float4*>(v)     = *reinterpret_cast<const float4*>(p + t * 8);
    *reinterpret_cast<float4*>(v + 4) = *reinterpret_cast<const float4*>(p + t * 8 + 4);

    float m = v[0];
#pragma unroll
    for (int i = 1; i < 8; i++) m = fmaxf(m, v[i]);
#pragma unroll
    for (int o = 16; o > 0; o >>= 1)
        m = fmaxf(m, __shfl_xor_sync(0xffffffffu, m, o));
    if (lane == 0) red[w] = m;
    __syncthreads();
    m = red[lane & 7];
#pragma unroll
    for (int o = 4; o > 0; o >>= 1)
        m = fmaxf(m, __shfl_xor_sync(0xffffffffu, m, o));

    float sum = 0.f;
#pragma unroll
    for (int i = 0; i < 8; i++) { v[i] = __expf(v[i] - m); sum += v[i]; }
#pragma unroll
    for (int o = 16; o > 0; o >>= 1)
        sum += __shfl_xor_sync(0xffffffffu, sum, o);
    __syncthreads();
    if (lane == 0) red[w] = sum;
    __syncthreads();
    sum = red[lane & 7];
#pragma unroll
    for (int o = 4; o > 0; o >>= 1)
        sum += __shfl_xor_sync(0xffffffffu, sum, o);
    const float inv = 1.f / sum;

    uint32_t hh[4], ll[4];
#pragma unroll
    for (int i = 0; i < 4; i++)
        split2(v[2 * i] * inv, v[2 * i + 1] * inv, hh[i], ll[i]);
    *reinterpret_cast<uint4*>(ph + ro + t * 8) = make_uint4(hh[0], hh[1], hh[2], hh[3]);
    *reinterpret_cast<uint4*>(pl + ro + t * 8) = make_uint4(ll[0], ll[1], ll[2], ll[3]);
}

// ---------------------------------------------------------------- launch
extern "C" void kernel_launch(void* const* d_in, const int* in_sizes, int n_in,
                              void* d_out, int out_size)
{
    const float* x  = (const float*)d_in[0];
    const float* Wq = (const float*)d_in[1];
    const float* bq = (const float*)d_in[2];
    const float* Wk = (const float*)d_in[3];
    const float* bk = (const float*)d_in[4];
    const float* Wv = (const float*)d_in[5];
    const float* bv = (const float*)d_in[6];
    float* out = (float*)d_out;

    int8_t* gi; __nv_bfloat16* bf; float* scp; float* scl;
    cudaGetSymbolAddress((void**)&gi,  g_i8);
    cudaGetSymbolAddress((void**)&bf,  g_bf);
    cudaGetSymbolAddress((void**)&scp, g_sc);
    cudaGetSymbolAddress((void**)&scl, g_scale);

    cudaFuncSetAttribute(qkv_i8,   cudaFuncAttributeMaxDynamicSharedMemorySize, SMEM_I8);
    cudaFuncSetAttribute(score_i8, cudaFuncAttributeMaxDynamicSharedMemorySize, SMEM_I8);
    cudaFuncSetAttribute(mma_o,    cudaFuncAttributeMaxDynamicSharedMemorySize, SMEM_BF);

    // 1-4: quantize x, Wq, Wk, Wv (per-row absmax -> int8 hi/lo + scale)
    quant_rows<<<8192 / 8, 256>>>(x,  gi + I_X1,  gi + I_X0,  scl + SX,  8192);
    quant_rows<<<1024 / 8, 256>>>(Wq, gi + I_WQ1, gi + I_WQ0, scl + SWQ, 1024);
    quant_rows<<<1024 / 8, 256>>>(Wk, gi + I_WK1, gi + I_WK0, scl + SWK, 1024);
    quant_rows<<<1024 / 8, 256>>>(Wv, gi + I_WV1, gi + I_WV0, scl + SWV, 1024);

    // 5: int8 fused QKV (Q,K fp32 -> g_sc; VT bf16 pairs)
    dim3 g_qkv(D / 128, (NB * S) / 128, 3);
    qkv_i8<<<g_qkv, 512, SMEM_I8>>>(bq, bk, bv);

    // 6-7: quantize Q, K rows
    quant_rows<<<8192 / 8, 256>>>(scp,      gi + I_Q1, gi + I_Q0, scl + SQ, 8192);
    quant_rows<<<8192 / 8, 256>>>(scp + NX, gi + I_K1, gi + I_K0, scl + SK, 8192);

    // 8: int8 score GEMM -> scores fp32 (overwrites Q/K fp32 region)
    dim3 g_sc_(S / 128, S / 128, NB);
    score_i8<<<g_sc_, 512, SMEM_I8>>>();

    // 9: softmax -> P bf16 pairs
    softmax_rows<<<NB * S, 256>>>(scp, bf + OPH, bf + OPL);

    // 10: O = P@VT^T (bf16x3) -> out
    dim3 g_o(D / 128, S / 128, NB);
    mma_o<<<g_o, 512, SMEM_BF>>>(out);
}

// round 14
// speedup vs baseline: 3.5200x; 3.5200x over previous
#include <cuda_runtime.h>
#include <cuda_fp16.h>
#include <cstdint>

// ============================================================================
// SelfAttention R14: fp16x2 asymmetric-split GEMMs (A: fp16-hi single plane,
// B: fp16 hi+lo pair), 2 HMMA passes per logical MMA (Ah*Bh + Ah*Bl).
// Precision bound: A rounding = tf32's 11-bit mantissa (R11 measured 4.9e-4
// with BOTH operands rounded) and B here is exact -> rel_err <= 4.9e-4.
// Structure = R12 winner: 512 thr, CTA 128x128, warp 32x32, K-chunk 64,
// 3-stage cp.async, fused QKV launch, shuffle softmax.
//   A-side arrays (x, Q, P): hi plane only. B-side (W, K, VT): hi + lo.
// ============================================================================

constexpr int S = 2048, D = 1024, NB = 4;
constexpr long SD  = (long)S * D;
constexpr long SSZ = (long)S * S;
constexpr long NX = (long)NB * S * D;
constexpr long NW = (long)D * D;
constexpr long NP = (long)NB * S * S;

// half-plane offsets
constexpr long OXH  = 0;
constexpr long OWQH = NX,        OWQL = NX + NW,
               OWKH = NX + 2*NW, OWKL = NX + 3*NW,
               OWVH = NX + 4*NW, OWVL = NX + 5*NW;
constexpr long OQH  = NX + 6*NW;
constexpr long OKH  = OQH + NX,   OKL  = OQH + 2*NX;
constexpr long OVTH = OQH + 3*NX, OVTL = OQH + 4*NX;
constexpr long OPH  = OQH + 5*NX;
constexpr long NHF  = OPH + NP;

__device__ __align__(128) __half g_hf[NHF];
__device__ float g_sc[NP];

constexpr int STAGE  = 48 * 1024;          // A 16KB | BH 16KB | BL 16KB
constexpr int OFF_A = 0, OFF_BH = 16384, OFF_BL = 32768;
constexpr int NSTG   = 3;
constexpr int SMEM_DYN = NSTG * STAGE + 1024;   // 148,480

#define SWZ(o) ((o) ^ (((o) >> 3) & 0x70))

// ---------------------------------------------------------------- helpers
__device__ __forceinline__ uint32_t smem_u32(const void* p) {
    uint32_t a;
    asm("{ .reg .u64 t; cvta.to.shared.u64 t, %1; cvt.u32.u64 %0, t; }"
        : "=r"(a) : "l"(p));
    return a;
}
__device__ __forceinline__ void ldsm4(uint32_t* r, uint32_t addr) {
    asm volatile("ldmatrix.sync.aligned.m8n8.x4.shared.b16 {%0,%1,%2,%3}, [%4];"
                 : "=r"(r[0]), "=r"(r[1]), "=r"(r[2]), "=r"(r[3]) : "r"(addr));
}
__device__ __forceinline__ void mma_f16(float* d, const uint32_t* a,
                                        const uint32_t* b) {
    asm volatile(
        "mma.sync.aligned.m16n8k16.row.col.f32.f16.f16.f32 "
        "{%0,%1,%2,%3}, {%4,%5,%6,%7}, {%8,%9}, {%0,%1,%2,%3};"
        : "+f"(d[0]), "+f"(d[1]), "+f"(d[2]), "+f"(d[3])
        : "r"(a[0]), "r"(a[1]), "r"(a[2]), "r"(a[3]), "r"(b[0]), "r"(b[1]));
}
#define CPA16(dst, src) \
    asm volatile("cp.async.cg.shared.global [%0], [%1], 16;" \
                 :: "r"(dst), "l"(src) : "memory")
#define CP_COMMIT() asm volatile("cp.async.commit_group;" ::: "memory")

// fp16 hi/lo split of two floats -> packed half2 words
__device__ __forceinline__ void split2h(float v0, float v1,
                                        uint32_t& h, uint32_t& l) {
    __half h0 = __float2half_rn(v0), h1 = __float2half_rn(v1);
    __half2 hh = __halves2half2(h0, h1);
    __half2 ll = __halves2half2(__float2half_rn(v0 - __half2float(h0)),
                                __float2half_rn(v1 - __half2float(h1)));
    h = *reinterpret_cast<uint32_t*>(&hh);
    l = *reinterpret_cast<uint32_t*>(&ll);
}
__device__ __forceinline__ uint32_t pack2h(float v0, float v1) {
    __half2 hh = __halves2half2(__float2half_rn(v0), __float2half_rn(v1));
    return *reinterpret_cast<uint32_t*>(&hh);
}

// ---------------------------------------------------------------- converter
// x -> hi plane only; Wq/Wk/Wv -> hi + lo planes. One launch.
__global__ void __launch_bounds__(256)
split_all(const float* __restrict__ x, const float* __restrict__ wq,
          const float* __restrict__ wk, const float* __restrict__ wv)
{
    const long i = ((long)blockIdx.x * 256 + threadIdx.x) * 4;
    const long total = NX + 3 * NW;
    if (i >= total) return;
    const float* src;
    long loc = i, oh, ol;
    bool has_lo = true;
    if (i < NX)               { src = x;  oh = OXH + i; ol = 0; has_lo = false; }
    else if (i < NX + NW)     { src = wq; loc = i - NX;
                                oh = OWQH + loc; ol = OWQL + loc; }
    else if (i < NX + 2 * NW) { src = wk; loc = i - NX - NW;
                                oh = OWKH + loc; ol = OWKL + loc; }
    else                      { src = wv; loc = i - NX - 2 * NW;
                                oh = OWVH + loc; ol = OWVL + loc; }
    float4 v = *reinterpret_cast<const float4*>(src + loc);
    if (has_lo) {
        uint2 h, l;
        split2h(v.x, v.y, h.x, l.x);
        split2h(v.z, v.w, h.y, l.y);
        *reinterpret_cast<uint2*>(&g_hf[0] + oh) = h;
        *reinterpret_cast<uint2*>(&g_hf[0] + ol) = l;
    } else {
        uint2 h;
        h.x = pack2h(v.x, v.y);
        h.y = pack2h(v.z, v.w);
        *reinterpret_cast<uint2*>(&g_hf[0] + oh) = h;
    }
}

// ---------------------------------------------------------------- mainloop
// 512 thr, 16 warps (4m x 4n), warp 32x32, CTA 128x128, K-chunk 64, 3 stages.
// A single plane, B hi+lo. Per ks: 6 ldsm.x4, 16 HMMA. acc[32].
__device__ __forceinline__ void gemm_mainloop(
    const __half* __restrict__ gA,
    const __half* __restrict__ gBh, const __half* __restrict__ gBl,
    int lda, int ldb, int K, uint32_t abase, float* acc)
{
    const int tid = threadIdx.x, lane = tid & 31, wid = tid >> 5;

    // loader: r0 = row (0..63)[+64], s0 = 16B seg (0..7); 6 cp.async/thread
    const int r0 = tid >> 3, s0 = tid & 7;
    const uint32_t w0 = SWZ((uint32_t)r0 * 128 + s0 * 16);
    const uint32_t w1 = SWZ((uint32_t)(r0 + 64) * 128 + s0 * 16);
    const __half* ga[6] = {
        gA  + (long)r0 * lda + s0 * 8,
        gA  + (long)(r0 + 64) * lda + s0 * 8,
        gBh + (long)r0 * ldb + s0 * 8,
        gBh + (long)(r0 + 64) * ldb + s0 * 8,
        gBl + (long)r0 * ldb + s0 * 8,
        gBl + (long)(r0 + 64) * ldb + s0 * 8 };
    const uint32_t soff[6] = { OFF_A + w0, OFF_A + w1, OFF_BH + w0, OFF_BH + w1,
                               OFF_BL + w0, OFF_BL + w1 };

    // fragment constants (warp 32x32 at (mw,nw))
    const int mw = (wid >> 2) * 32, nw = (wid & 3) * 32;
    uint32_t a_row[2], a_swz[2];
#pragma unroll
    for (int i = 0; i < 2; i++) {
        uint32_t rb = (uint32_t)(mw + 16 * i + (lane & 15)) * 128;
        a_row[i] = rb; a_swz[i] = (rb >> 3) & 0x70;
    }
    const uint32_t a_kl = (uint32_t)((lane >> 4) << 4);
    uint32_t b_row[2], b_swz[2];
#pragma unroll
    for (int p = 0; p < 2; p++) {
        uint32_t rb = (uint32_t)(nw + 16 * p + (lane & 7) + ((lane & 16) >> 1)) * 128;
        b_row[p] = rb; b_swz[p] = (rb >> 3) & 0x70;
    }
    const uint32_t b_kl = (uint32_t)((lane & 8) << 1);

    const int nch = K >> 6;

#define ISSUE(ch) do {                                                        \
        const uint32_t _sb = abase + (uint32_t)((ch) % NSTG) * STAGE;         \
        const long _k = (long)(ch) * 64;                                      \
        _Pragma("unroll")                                                     \
        for (int q = 0; q < 6; q++) CPA16(_sb + soff[q], ga[q] + _k);         \
        CP_COMMIT();                                                          \
    } while (0)

    ISSUE(0);
    ISSUE(1);

    for (int ch = 0; ch < nch; ch++) {
        if (ch + 1 < nch)
            asm volatile("cp.async.wait_group 1;" ::: "memory");
        else
            asm volatile("cp.async.wait_group 0;" ::: "memory");
        __syncthreads();
        if (ch + 2 < nch) ISSUE(ch + 2);

        const uint32_t sb = abase + (uint32_t)(ch % NSTG) * STAGE;
#pragma unroll
        for (int ks = 0; ks < 4; ks++) {
            const uint32_t KB = ks * 32;
            uint32_t af[2][4], bh[8], bl[8];
#pragma unroll
            for (int i = 0; i < 2; i++)
                ldsm4(af[i], sb + OFF_A + a_row[i] + ((KB + a_kl) ^ a_swz[i]));
#pragma unroll
            for (int p = 0; p < 2; p++) {
                const uint32_t ko = KB + b_kl;
                ldsm4(&bh[4 * p], sb + OFF_BH + b_row[p] + (ko ^ b_swz[p]));
                ldsm4(&bl[4 * p], sb + OFF_BL + b_row[p] + (ko ^ b_swz[p]));
            }
#pragma unroll
            for (int i = 0; i < 2; i++)
#pragma unroll
                for (int j = 0; j < 4; j++)
                    mma_f16(acc + (i * 4 + j) * 4, af[i], &bh[j * 2]);  // Ah*Bh
#pragma unroll
            for (int i = 0; i < 2; i++)
#pragma unroll
                for (int j = 0; j < 4; j++)
                    mma_f16(acc + (i * 4 + j) * 4, af[i], &bl[j * 2]);  // Ah*Bl
        }
    }
#undef ISSUE
}

// ---------------------------------------------------------------- fused QKV
// grid (8, 64, 3): z=0 -> Q hi (row-major), z=1 -> K hi+lo (row-major),
// z=2 -> VT hi+lo (per-batch transposed, ld=S, smem-staged).
__global__ void __launch_bounds__(512, 1)
mma_qkv(const float* __restrict__ bq, const float* __restrict__ bk,
        const float* __restrict__ bv)
{
    const int z = blockIdx.z;
    const long row0 = (long)blockIdx.y * 128, col0 = (long)blockIdx.x * 128;

    extern __shared__ char smem_raw[];
    const uint32_t rawb  = smem_u32(smem_raw);
    const uint32_t abase = (rawb + 1023) & ~1023u;
    char* smem = smem_raw + (abase - rawb);

    const __half* Wh = &g_hf[z == 0 ? OWQH : z == 1 ? OWKH : OWVH];
    const __half* Wl = &g_hf[z == 0 ? OWQL : z == 1 ? OWKL : OWVL];
    const float* bias = z == 0 ? bq : z == 1 ? bk : bv;

    float acc[32];
#pragma unroll
    for (int i = 0; i < 32; i++) acc[i] = 0.f;

    gemm_mainloop(&g_hf[OXH] + row0 * D, Wh + col0 * D, Wl + col0 * D,
                  D, D, D, abase, acc);

    const int tid = threadIdx.x, lane = tid & 31, wid = tid >> 5;
    const int mw = (wid >> 2) * 32, nw = (wid & 3) * 32;
    const int qr = lane >> 2, qc = lane & 3;

    if (z == 0) {
        __half* Ch = &g_hf[OQH];
#pragma unroll
        for (int i = 0; i < 2; i++)
#pragma unroll
            for (int j = 0; j < 4; j++) {
                const float* d = acc + (i * 4 + j) * 4;
#pragma unroll
                for (int h = 0; h < 2; h++) {
                    const long r = row0 + mw + 16 * i + qr + 8 * h;
                    const long c = col0 + nw + 8 * j + 2 * qc;
                    *reinterpret_cast<uint32_t*>(&Ch[r * D + c]) =
                        pack2h(d[2 * h] + bias[c], d[2 * h + 1] + bias[c + 1]);
                }
            }
    } else if (z == 1) {
        __half* Ch = &g_hf[OKH];
        __half* Cl = &g_hf[OKL];
#pragma unroll
        for (int i = 0; i < 2; i++)
#pragma unroll
            for (int j = 0; j < 4; j++) {
                const float* d = acc + (i * 4 + j) * 4;
#pragma unroll
                for (int h = 0; h < 2; h++) {
                    const long r = row0 + mw + 16 * i + qr + 8 * h;
                    const long c = col0 + nw + 8 * j + 2 * qc;
                    uint32_t hh, ll;
                    split2h(d[2 * h] + bias[c], d[2 * h + 1] + bias[c + 1], hh, ll);
                    *reinterpret_cast<uint32_t*>(&Ch[r * D + c]) = hh;
                    *reinterpret_cast<uint32_t*>(&Cl[r * D + c]) = ll;
                }
            }
    } else {
        // VT: stage hi/lo transposed tiles in smem, coalesced 16B stores.
        const long b = row0 >> 11, rloc = row0 & (S - 1);
        __half* Ch = &g_hf[OVTH] + b * SD;
        __half* Cl = &g_hf[OVTL] + b * SD;
        __syncthreads();
        __half* sh = reinterpret_cast<__half*>(smem);
        __half* sl = sh + 128 * 136;
#pragma unroll
        for (int i = 0; i < 2; i++)
#pragma unroll
            for (int j = 0; j < 4; j++) {
                const float* d = acc + (i * 4 + j) * 4;
#pragma unroll
                for (int h = 0; h < 2; h++) {
                    const int rl = mw + 16 * i + qr + 8 * h;
                    const int cl = nw + 8 * j + 2 * qc;
                    float v0 = d[2 * h] + bias[col0 + cl];
                    float v1 = d[2 * h + 1] + bias[col0 + cl + 1];
                    __half h0 = __float2half_rn(v0);
                    __half h1 = __float2half_rn(v1);
                    sh[cl * 136 + rl]       = h0;
                    sh[(cl + 1) * 136 + rl] = h1;
                    sl[cl * 136 + rl] =
                        __float2half_rn(v0 - __half2float(h0));
                    sl[(cl + 1) * 136 + rl] =
                        __float2half_rn(v1 - __half2float(h1));
                }
            }
        __syncthreads();
        const int c = tid >> 2, seg = tid & 3;   // 128 cols x 4 segs of 32 elems
        const __half* srh = sh + c * 136 + seg * 32;
        const __half* srl = sl + c * 136 + seg * 32;
        __half* dsh = Ch + (col0 + c) * (long)S + rloc + seg * 32;
        __half* dsl = Cl + (col0 + c) * (long)S + rloc + seg * 32;
#pragma unroll
        for (int q = 0; q < 4; q++) {
            *reinterpret_cast<uint4*>(dsh + q * 8) =
                *reinterpret_cast<const uint4*>(srh + q * 8);
            *reinterpret_cast<uint4*>(dsl + q * 8) =
                *reinterpret_cast<const uint4*>(srl + q * 8);
        }
    }
}

// ---------------------------------------------------------------- generic GEMM
// fp32 out: Cf[r*ldc + c] = scale * A@B^T. Batched by blockIdx.z.
__global__ void __launch_bounds__(512, 1)
mma_gemm(const __half* __restrict__ A,
         const __half* __restrict__ Bh, const __half* __restrict__ Bl,
         float* __restrict__ Cf, int K, int lda, int ldb, int ldc,
         long sA, long sB, long sC, float scale)
{
    const long zb = blockIdx.z;
    const long row0 = (long)blockIdx.y * 128, col0 = (long)blockIdx.x * 128;

    extern __shared__ char smem_raw[];
    const uint32_t rawb  = smem_u32(smem_raw);
    const uint32_t abase = (rawb + 1023) & ~1023u;

    float acc[32];
#pragma unroll
    for (int i = 0; i < 32; i++) acc[i] = 0.f;

    gemm_mainloop(A + sA * zb + row0 * (long)lda,
                  Bh + sB * zb + col0 * (long)ldb,
                  Bl + sB * zb + col0 * (long)ldb,
                  lda, ldb, K, abase, acc);

    float* Cp = Cf + sC * zb;
    const int tid = threadIdx.x, lane = tid & 31, wid = tid >> 5;
    const int mw = (wid >> 2) * 32, nw = (wid & 3) * 32;
    const int qr = lane >> 2, qc = lane & 3;
#pragma unroll
    for (int i = 0; i < 2; i++)
#pragma unroll
        for (int j = 0; j < 4; j++) {
            const float* d = acc + (i * 4 + j) * 4;
#pragma unroll
            for (int h = 0; h < 2; h++) {
                const long r = row0 + mw + 16 * i + qr + 8 * h;
                const long c = col0 + nw + 8 * j + 2 * qc;
                *reinterpret_cast<float2*>(&Cp[r * (long)ldc + c]) =
                    make_float2(d[2 * h] * scale, d[2 * h + 1] * scale);
            }
        }
}

// ---------------------------------------------------------------- softmax
// P output: fp16 hi plane only (A-side of the O GEMM).
__global__ void __launch_bounds__(256)
softmax_rows(const float* __restrict__ sc, __half* __restrict__ ph)
{
    const long ro = (long)blockIdx.x * 2048;
    const float* p = sc + ro;
    __shared__ float red[8];
    const int t = threadIdx.x, lane = t & 31, w = t >> 5;

    float v[8];
    *reinterpret_cast<float4*>(v)     = *reinterpret_cast<const float4*>(p + t * 8);
    *reinterpret_cast<float4*>(v + 4) = *reinterpret_cast<const float4*>(p + t * 8 + 4);

    float m = v[0];
#pragma unroll
    for (int i = 1; i < 8; i++) m = fmaxf(m, v[i]);
#pragma unroll
    for (int o = 16; o > 0; o >>= 1)
        m = fmaxf(m, __shfl_xor_sync(0xffffffffu, m, o));
    if (lane == 0) red[w] = m;
    __syncthreads();
    m = red[lane & 7];
#pragma unroll
    for (int o = 4; o > 0; o >>= 1)
        m = fmaxf(m, __shfl_xor_sync(0xffffffffu, m, o));

    float sum = 0.f;
#pragma unroll
    for (int i = 0; i < 8; i++) { v[i] = __expf(v[i] - m); sum += v[i]; }
#pragma unroll
    for (int o = 16; o > 0; o >>= 1)
        sum += __shfl_xor_sync(0xffffffffu, sum, o);
    __syncthreads();
    if (lane == 0) red[w] = sum;
    __syncthreads();
    sum = red[lane & 7];
#pragma unroll
    for (int o = 4; o > 0; o >>= 1)
        sum += __shfl_xor_sync(0xffffffffu, sum, o);
    const float inv = 1.f / sum;

    uint32_t hh[4];
#pragma unroll
    for (int i = 0; i < 4; i++)
        hh[i] = pack2h(v[2 * i] * inv, v[2 * i + 1] * inv);
    *reinterpret_cast<uint4*>(ph + ro + t * 8) =
        make_uint4(hh[0], hh[1], hh[2], hh[3]);
}

// ---------------------------------------------------------------- launch
extern "C" void kernel_launch(void* const* d_in, const int* in_sizes, int n_in,
                              void* d_out, int out_size)
{
    const float* x  = (const float*)d_in[0];
    const float* Wq = (const float*)d_in[1];
    const float* bq = (const float*)d_in[2];
    const float* Wk = (const float*)d_in[3];
    const float* bk = (const float*)d_in[4];
    const float* Wv = (const float*)d_in[5];
    const float* bv = (const float*)d_in[6];
    float* out = (float*)d_out;

    __half* hf; float* scp;
    cudaGetSymbolAddress((void**)&hf, g_hf);
    cudaGetSymbolAddress((void**)&scp, g_sc);

    cudaFuncSetAttribute(mma_qkv, cudaFuncAttributeMaxDynamicSharedMemorySize,
                         SMEM_DYN);
    cudaFuncSetAttribute(mma_gemm, cudaFuncAttributeMaxDynamicSharedMemorySize,
                         SMEM_DYN);
    dim3 thr(512);

    // launch 1: merged converter (x hi; W hi+lo)
    const long tot = NX + 3 * NW;
    split_all<<<(int)((tot / 4 + 255) / 256), 256>>>(x, Wq, Wk, Wv);

    // launch 2: fused Q/K/VT projections
    dim3 g_qkv(D / 128, (NB * S) / 128, 3);
    mma_qkv<<<g_qkv, thr, SMEM_DYN>>>(bq, bk, bv);

    // launch 3: Sc = Q@K^T / 32 (fp32), batched. A = Q-hi, B = K hi+lo.
    dim3 g_sc(S / 128, S / 128, NB);
    mma_gemm<<<g_sc, thr, SMEM_DYN>>>(hf + OQH, hf + OKH, hf + OKL,
                                      scp, D, D, D, S, SD, SD, SSZ, 0.03125f);

    // launch 4: softmax -> P hi
    softmax_rows<<<NB * S, 256>>>(scp, hf + OPH);

    // launch 5: O = P@VT^T (fp32), batched, K = S. A = P-hi, B = VT hi+lo.
    dim3 g_o(D / 128, S / 128, NB);
    mma_gemm<<<g_o, thr, SMEM_DYN>>>(hf + OPH, hf + OVTH, hf + OVTL,
                                     out, S, S, S, D, SSZ, SD, SD, 1.f);
}

// round 15
// speedup vs baseline: 5.4540x; 1.5494x over previous
#include <cuda_runtime.h>
#include <cuda_fp16.h>
#include <cstdint>

// ============================================================================
// SelfAttention R15: single-pass fp16 HMMA GEMMs (both operands fp16-rounded,
// 11-bit mantissa). Error anchor: R11 measured 4.9e-4 with the same rounding
// configuration (tf32, same mantissa) end-to-end -> expected ~5e-4 < 1e-3.
// vs R14: tensor work x0.5, LDSM x0.67, cp.async x0.67. Structure = R12/R14
// winner: 512 thr, CTA 128x128, warp 32x32, K-chunk 64, 3-stage cp.async,
// fused QKV launch, shuffle softmax.
// ============================================================================

constexpr int S = 2048, D = 1024, NB = 4;
constexpr long SD  = (long)S * D;
constexpr long SSZ = (long)S * S;
constexpr long NX = (long)NB * S * D;
constexpr long NW = (long)D * D;
constexpr long NP = (long)NB * S * S;

constexpr long OXH  = 0;
constexpr long OWQH = NX, OWKH = NX + NW, OWVH = NX + 2 * NW;
constexpr long OQH  = NX + 3 * NW;
constexpr long OKH  = OQH + NX;
constexpr long OVTH = OQH + 2 * NX;
constexpr long OPH  = OQH + 3 * NX;
constexpr long NHF  = OPH + NP;

__device__ __align__(128) __half g_hf[NHF];
__device__ float g_sc[NP];

constexpr int STAGE = 32 * 1024;           // A 16KB | B 16KB
constexpr int OFF_B = 16384;
constexpr int NSTG  = 3;
constexpr int SMEM_DYN = NSTG * STAGE + 1024;   // 99,328

#define SWZ(o) ((o) ^ (((o) >> 3) & 0x70))

// ---------------------------------------------------------------- helpers
__device__ __forceinline__ uint32_t smem_u32(const void* p) {
    uint32_t a;
    asm("{ .reg .u64 t; cvta.to.shared.u64 t, %1; cvt.u32.u64 %0, t; }"
        : "=r"(a) : "l"(p));
    return a;
}
__device__ __forceinline__ void ldsm4(uint32_t* r, uint32_t addr) {
    asm volatile("ldmatrix.sync.aligned.m8n8.x4.shared.b16 {%0,%1,%2,%3}, [%4];"
                 : "=r"(r[0]), "=r"(r[1]), "=r"(r[2]), "=r"(r[3]) : "r"(addr));
}
__device__ __forceinline__ void mma_f16(float* d, const uint32_t* a,
                                        const uint32_t* b) {
    asm volatile(
        "mma.sync.aligned.m16n8k16.row.col.f32.f16.f16.f32 "
        "{%0,%1,%2,%3}, {%4,%5,%6,%7}, {%8,%9}, {%0,%1,%2,%3};"
        : "+f"(d[0]), "+f"(d[1]), "+f"(d[2]), "+f"(d[3])
        : "r"(a[0]), "r"(a[1]), "r"(a[2]), "r"(a[3]), "r"(b[0]), "r"(b[1]));
}
#define CPA16(dst, src) \
    asm volatile("cp.async.cg.shared.global [%0], [%1], 16;" \
                 :: "r"(dst), "l"(src) : "memory")
#define CP_COMMIT() asm volatile("cp.async.commit_group;" ::: "memory")

__device__ __forceinline__ uint32_t pack2h(float v0, float v1) {
    __half2 hh = __halves2half2(__float2half_rn(v0), __float2half_rn(v1));
    return *reinterpret_cast<uint32_t*>(&hh);
}

// ---------------------------------------------------------------- converter
// One launch: x, Wq, Wk, Wv -> fp16 single plane each (contiguous layout).
__global__ void __launch_bounds__(256)
conv_all(const float* __restrict__ x, const float* __restrict__ wq,
         const float* __restrict__ wk, const float* __restrict__ wv)
{
    const long i = ((long)blockIdx.x * 256 + threadIdx.x) * 4;
    const long total = NX + 3 * NW;
    if (i >= total) return;
    const float* src;
    long loc = i;
    if (i < NX)               { src = x; }
    else if (i < NX + NW)     { src = wq; loc = i - NX; }
    else if (i < NX + 2 * NW) { src = wk; loc = i - NX - NW; }
    else                      { src = wv; loc = i - NX - 2 * NW; }
    float4 v = *reinterpret_cast<const float4*>(src + loc);
    uint2 h;
    h.x = pack2h(v.x, v.y);
    h.y = pack2h(v.z, v.w);
    *reinterpret_cast<uint2*>(&g_hf[0] + i) = h;   // layout is contiguous
}

// ---------------------------------------------------------------- mainloop
// 512 thr, 16 warps (4m x 4n), warp 32x32, CTA 128x128, K-chunk 64, 3 stages.
// Single fp16 plane per operand. Per ks: 4 ldsm.x4, 8 HMMA. acc[32].
__device__ __forceinline__ void gemm_mainloop(
    const __half* __restrict__ gA, const __half* __restrict__ gB,
    int lda, int ldb, int K, uint32_t abase, float* acc)
{
    const int tid = threadIdx.x, lane = tid & 31, wid = tid >> 5;

    // loader: r0 = row (0..63)[+64], s0 = 16B seg (0..7); 4 cp.async/thread
    const int r0 = tid >> 3, s0 = tid & 7;
    const uint32_t w0 = SWZ((uint32_t)r0 * 128 + s0 * 16);
    const uint32_t w1 = SWZ((uint32_t)(r0 + 64) * 128 + s0 * 16);
    const __half* ga[4] = {
        gA + (long)r0 * lda + s0 * 8,
        gA + (long)(r0 + 64) * lda + s0 * 8,
        gB + (long)r0 * ldb + s0 * 8,
        gB + (long)(r0 + 64) * ldb + s0 * 8 };
    const uint32_t soff[4] = { w0, w1, OFF_B + w0, OFF_B + w1 };

    // fragment constants (warp 32x32 at (mw,nw))
    const int mw = (wid >> 2) * 32, nw = (wid & 3) * 32;
    uint32_t a_row[2], a_swz[2];
#pragma unroll
    for (int i = 0; i < 2; i++) {
        uint32_t rb = (uint32_t)(mw + 16 * i + (lane & 15)) * 128;
        a_row[i] = rb; a_swz[i] = (rb >> 3) & 0x70;
    }
    const uint32_t a_kl = (uint32_t)((lane >> 4) << 4);
    uint32_t b_row[2], b_swz[2];
#pragma unroll
    for (int p = 0; p < 2; p++) {
        uint32_t rb = (uint32_t)(nw + 16 * p + (lane & 7) + ((lane & 16) >> 1)) * 128;
        b_row[p] = rb; b_swz[p] = (rb >> 3) & 0x70;
    }
    const uint32_t b_kl = (uint32_t)((lane & 8) << 1);

    const int nch = K >> 6;

#define ISSUE(ch) do {                                                        \
        const uint32_t _sb = abase + (uint32_t)((ch) % NSTG) * STAGE;         \
        const long _k = (long)(ch) * 64;                                      \
        _Pragma("unroll")                                                     \
        for (int q = 0; q < 4; q++) CPA16(_sb + soff[q], ga[q] + _k);         \
        CP_COMMIT();                                                          \
    } while (0)

    ISSUE(0);
    ISSUE(1);

    for (int ch = 0; ch < nch; ch++) {
        if (ch + 1 < nch)
            asm volatile("cp.async.wait_group 1;" ::: "memory");
        else
            asm volatile("cp.async.wait_group 0;" ::: "memory");
        __syncthreads();
        if (ch + 2 < nch) ISSUE(ch + 2);

        const uint32_t sb = abase + (uint32_t)(ch % NSTG) * STAGE;
#pragma unroll
        for (int ks = 0; ks < 4; ks++) {
            const uint32_t KB = ks * 32;
            uint32_t af[2][4], bf[8];
#pragma unroll
            for (int i = 0; i < 2; i++)
                ldsm4(af[i], sb + a_row[i] + ((KB + a_kl) ^ a_swz[i]));
#pragma unroll
            for (int p = 0; p < 2; p++)
                ldsm4(&bf[4 * p], sb + OFF_B + b_row[p] +
                                  ((KB + b_kl) ^ b_swz[p]));
#pragma unroll
            for (int i = 0; i < 2; i++)
#pragma unroll
                for (int j = 0; j < 4; j++)
                    mma_f16(acc + (i * 4 + j) * 4, af[i], &bf[j * 2]);
        }
    }
#undef ISSUE
}

// ---------------------------------------------------------------- fused QKV
// grid (8, 64, 3): z=0 Q, z=1 K (row-major fp16), z=2 VT (transposed fp16).
__global__ void __launch_bounds__(512, 1)
mma_qkv(const float* __restrict__ bq, const float* __restrict__ bk,
        const float* __restrict__ bv)
{
    const int z = blockIdx.z;
    const long row0 = (long)blockIdx.y * 128, col0 = (long)blockIdx.x * 128;

    extern __shared__ char smem_raw[];
    const uint32_t rawb  = smem_u32(smem_raw);
    const uint32_t abase = (rawb + 1023) & ~1023u;
    char* smem = smem_raw + (abase - rawb);

    const __half* W = &g_hf[z == 0 ? OWQH : z == 1 ? OWKH : OWVH];
    const float* bias = z == 0 ? bq : z == 1 ? bk : bv;

    float acc[32];
#pragma unroll
    for (int i = 0; i < 32; i++) acc[i] = 0.f;

    gemm_mainloop(&g_hf[OXH] + row0 * D, W + col0 * D, D, D, D, abase, acc);

    const int tid = threadIdx.x, lane = tid & 31, wid = tid >> 5;
    const int mw = (wid >> 2) * 32, nw = (wid & 3) * 32;
    const int qr = lane >> 2, qc = lane & 3;

    if (z < 2) {
        __half* Ch = &g_hf[z == 0 ? OQH : OKH];
#pragma unroll
        for (int i = 0; i < 2; i++)
#pragma unroll
            for (int j = 0; j < 4; j++) {
                const float* d = acc + (i * 4 + j) * 4;
#pragma unroll
                for (int h = 0; h < 2; h++) {
                    const long r = row0 + mw + 16 * i + qr + 8 * h;
                    const long c = col0 + nw + 8 * j + 2 * qc;
                    *reinterpret_cast<uint32_t*>(&Ch[r * D + c]) =
                        pack2h(d[2 * h] + bias[c], d[2 * h + 1] + bias[c + 1]);
                }
            }
    } else {
        // VT: stage transposed fp16 tile in smem, coalesced 16B stores.
        const long b = row0 >> 11, rloc = row0 & (S - 1);
        __half* Ch = &g_hf[OVTH] + b * SD;
        __syncthreads();
        __half* sh = reinterpret_cast<__half*>(smem);
#pragma unroll
        for (int i = 0; i < 2; i++)
#pragma unroll
            for (int j = 0; j < 4; j++) {
                const float* d = acc + (i * 4 + j) * 4;
#pragma unroll
                for (int h = 0; h < 2; h++) {
                    const int rl = mw + 16 * i + qr + 8 * h;
                    const int cl = nw + 8 * j + 2 * qc;
                    sh[cl * 136 + rl] =
                        __float2half_rn(d[2 * h] + bias[col0 + cl]);
                    sh[(cl + 1) * 136 + rl] =
                        __float2half_rn(d[2 * h + 1] + bias[col0 + cl + 1]);
                }
            }
        __syncthreads();
        const int c = tid >> 2, seg = tid & 3;   // 128 cols x 4 segs of 32 elems
        const __half* sr = sh + c * 136 + seg * 32;
        __half* ds = Ch + (col0 + c) * (long)S + rloc + seg * 32;
#pragma unroll
        for (int q = 0; q < 4; q++)
            *reinterpret_cast<uint4*>(ds + q * 8) =
                *reinterpret_cast<const uint4*>(sr + q * 8);
    }
}

// ---------------------------------------------------------------- generic GEMM
// fp32 out: Cf[r*ldc + c] = scale * A@B^T. Batched by blockIdx.z.
__global__ void __launch_bounds__(512, 1)
mma_gemm(const __half* __restrict__ A, const __half* __restrict__ B,
         float* __restrict__ Cf, int K, int lda, int ldb, int ldc,
         long sA, long sB, long sC, float scale)
{
    const long zb = blockIdx.z;
    const long row0 = (long)blockIdx.y * 128, col0 = (long)blockIdx.x * 128;

    extern __shared__ char smem_raw[];
    const uint32_t rawb  = smem_u32(smem_raw);
    const uint32_t abase = (rawb + 1023) & ~1023u;

    float acc[32];
#pragma unroll
    for (int i = 0; i < 32; i++) acc[i] = 0.f;

    gemm_mainloop(A + sA * zb + row0 * (long)lda,
                  B + sB * zb + col0 * (long)ldb, lda, ldb, K, abase, acc);

    float* Cp = Cf + sC * zb;
    const int tid = threadIdx.x, lane = tid & 31, wid = tid >> 5;
    const int mw = (wid >> 2) * 32, nw = (wid & 3) * 32;
    const int qr = lane >> 2, qc = lane & 3;
#pragma unroll
    for (int i = 0; i < 2; i++)
#pragma unroll
        for (int j = 0; j < 4; j++) {
            const float* d = acc + (i * 4 + j) * 4;
#pragma unroll
            for (int h = 0; h < 2; h++) {
                const long r = row0 + mw + 16 * i + qr + 8 * h;
                const long c = col0 + nw + 8 * j + 2 * qc;
                *reinterpret_cast<float2*>(&Cp[r * (long)ldc + c]) =
                    make_float2(d[2 * h] * scale, d[2 * h + 1] * scale);
            }
        }
}

// ---------------------------------------------------------------- softmax
__global__ void __launch_bounds__(256)
softmax_rows(const float* __restrict__ sc, __half* __restrict__ ph)
{
    const long ro = (long)blockIdx.x * 2048;
    const float* p = sc + ro;
    __shared__ float red[8];
    const int t = threadIdx.x, lane = t & 31, w = t >> 5;

    float v[8];
    *reinterpret_cast<float4*>(v)     = *reinterpret_cast<const float4*>(p + t * 8);
    *reinterpret_cast<float4*>(v + 4) = *reinterpret_cast<const float4*>(p + t * 8 + 4);

    float m = v[0];
#pragma unroll
    for (int i = 1; i < 8; i++) m = fmaxf(m, v[i]);
#pragma unroll
    for (int o = 16; o > 0; o >>= 1)
        m = fmaxf(m, __shfl_xor_sync(0xffffffffu, m, o));
    if (lane == 0) red[w] = m;
    __syncthreads();
    m = red[lane & 7];
#pragma unroll
    for (int o = 4; o > 0; o >>= 1)
        m = fmaxf(m, __shfl_xor_sync(0xffffffffu, m, o));

    float sum = 0.f;
#pragma unroll
    for (int i = 0; i < 8; i++) { v[i] = __expf(v[i] - m); sum += v[i]; }
#pragma unroll
    for (int o = 16; o > 0; o >>= 1)
        sum += __shfl_xor_sync(0xffffffffu, sum, o);
    __syncthreads();
    if (lane == 0) red[w] = sum;
    __syncthreads();
    sum = red[lane & 7];
#pragma unroll
    for (int o = 4; o > 0; o >>= 1)
        sum += __shfl_xor_sync(0xffffffffu, sum, o);
    const float inv = 1.f / sum;

    uint32_t hh[4];
#pragma unroll
    for (int i = 0; i < 4; i++)
        hh[i] = pack2h(v[2 * i] * inv, v[2 * i + 1] * inv);
    *reinterpret_cast<uint4*>(ph + ro + t * 8) =
        make_uint4(hh[0], hh[1], hh[2], hh[3]);
}

// ---------------------------------------------------------------- launch
extern "C" void kernel_launch(void* const* d_in, const int* in_sizes, int n_in,
                              void* d_out, int out_size)
{
    const float* x  = (const float*)d_in[0];
    const float* Wq = (const float*)d_in[1];
    const float* bq = (const float*)d_in[2];
    const float* Wk = (const float*)d_in[3];
    const float* bk = (const float*)d_in[4];
    const float* Wv = (const float*)d_in[5];
    const float* bv = (const float*)d_in[6];
    float* out = (float*)d_out;

    __half* hf; float* scp;
    cudaGetSymbolAddress((void**)&hf, g_hf);
    cudaGetSymbolAddress((void**)&scp, g_sc);

    cudaFuncSetAttribute(mma_qkv, cudaFuncAttributeMaxDynamicSharedMemorySize,
                         SMEM_DYN);
    cudaFuncSetAttribute(mma_gemm, cudaFuncAttributeMaxDynamicSharedMemorySize,
                         SMEM_DYN);
    dim3 thr(512);

    // launch 1: merged fp16 converter
    const long tot = NX + 3 * NW;
    conv_all<<<(int)((tot / 4 + 255) / 256), 256>>>(x, Wq, Wk, Wv);

    // launch 2: fused Q/K/VT projections
    dim3 g_qkv(D / 128, (NB * S) / 128, 3);
    mma_qkv<<<g_qkv, thr, SMEM_DYN>>>(bq, bk, bv);

    // launch 3: Sc = Q@K^T / 32 (fp32), batched
    dim3 g_sc(S / 128, S / 128, NB);
    mma_gemm<<<g_sc, thr, SMEM_DYN>>>(hf + OQH, hf + OKH,
                                      scp, D, D, D, S, SD, SD, SSZ, 0.03125f);

    // launch 4: softmax -> P fp16
    softmax_rows<<<NB * S, 256>>>(scp, hf + OPH);

    // launch 5: O = P@VT^T (fp32), batched, K = S
    dim3 g_o(D / 128, S / 128, NB);
    mma_gemm<<<g_o, thr, SMEM_DYN>>>(hf + OPH, hf + OVTH,
                                     out, S, S, S, D, SSZ, SD, SD, 1.f);
}